// round 11
// baseline (speedup 1.0000x reference)
#include <cuda_runtime.h>

typedef unsigned long long ull;

constexpr int cN = 256, cC = 64, cT = 128, cV = 25, cO = 64;
constexpr int TV  = cT * cV;          // 3200 contiguous (t,v) per (n, channel)

// scratch (no allocations allowed)
__device__ float g_xsum[cN * cC * cV];                    // 1.6 MB
__device__ float g_att[(size_t)cN * cO * cV * cV];        // 41 MB
__device__ float g_vten[(size_t)cN * cO * TV];            // 210 MB

// ---------------------------------------------------------------------------
// K1: xsum[n,c,v] = sum_t x[n,c,t,v]   (HBM-roof bound, ~40us, keep)
// ---------------------------------------------------------------------------
__global__ void k_sum_t(const float* __restrict__ x) {
    int n = blockIdx.y;
    int c = blockIdx.x * 8 + (threadIdx.x >> 5);
    int lane = threadIdx.x & 31;
    if (lane < cV) {
        const float* p = x + ((size_t)(n * cC + c) * cT) * cV + lane;
        float s = 0.f;
        #pragma unroll 8
        for (int t = 0; t < cT; ++t) s += p[t * cV];
        g_xsum[(n * cC + c) * cV + lane] = s;
    }
}

// ---------------------------------------------------------------------------
// K2: attention matrix. grid (2, N): o-halves. Phase A: tanh features into
// smem aa[p][9]; phase B: p-coalesced stores of g_att[n,o,p].
// alpha folded into fw/fb so phase B is pure FMA + coalesced STG.
// ---------------------------------------------------------------------------
__global__ void __launch_bounds__(256) k_att_kernel(
    const float* __restrict__ adj,
    const float* __restrict__ Wk, const float* __restrict__ bk,
    const float* __restrict__ Wq, const float* __restrict__ bq,
    const float* __restrict__ c1w, const float* __restrict__ c1b,
    const float* __restrict__ c2w, const float* __restrict__ c2b,
    const float* __restrict__ fw,  const float* __restrict__ fb,
    const float* __restrict__ alpha) {
    __shared__ float xs2[cC * cV];
    __shared__ float ksh[4 * cV], qsh[4 * cV];
    __shared__ float fwal[cO * 8];              // alpha * fw
    __shared__ float adjsh[cV * cV];
    __shared__ float aa[625 * 9];               // tanh features, stride 9
    __shared__ float c1sh[16], c2sh[16], c1bs[4], c2bs[4], fbal[cO], bks[4], bqs[4];

    int n = blockIdx.y, oh = blockIdx.x, tid = threadIdx.x;
    float al = alpha[0];
    for (int i = tid; i < cC * cV; i += 256) xs2[i] = g_xsum[n * cC * cV + i];
    for (int i = tid; i < cO * 8; i += 256)  fwal[i] = al * fw[i];
    for (int i = tid; i < cV * cV; i += 256) adjsh[i] = adj[i];
    if (tid < 16) { c1sh[tid] = c1w[tid]; c2sh[tid] = c2w[tid]; }
    if (tid < 4)  { c1bs[tid] = c1b[tid]; c2bs[tid] = c2b[tid]; bks[tid] = bk[tid]; bqs[tid] = bq[tid]; }
    if (tid < cO) fbal[tid] = al * fb[tid];
    __syncthreads();

    if (tid < 100) {
        int r = tid / cV, v = tid % cV;
        float a = 0.f;
        for (int c = 0; c < cC; ++c) a += Wk[r * cC + c] * xs2[c * cV + v];
        ksh[tid] = a * (1.f / cT) + bks[r];
    } else if (tid < 200) {
        int j = tid - 100;
        int r = j / cV, v = j % cV;
        float a = 0.f;
        for (int c = 0; c < cC; ++c) a += Wq[r * cC + c] * xs2[c * cV + v];
        qsh[j] = a * (1.f / cT) + bqs[r];
    }
    __syncthreads();

    // phase A: features
    for (int p = tid; p < 625; p += 256) {
        int v = p / cV, u = p - v * cV;
        float kv[4], qu[4];
        #pragma unroll
        for (int r = 0; r < 4; ++r) { kv[r] = ksh[r * cV + v]; qu[r] = qsh[r * cV + u]; }
        #pragma unroll
        for (int s = 0; s < 4; ++s) {
            float s1 = c1bs[s], s2 = c2bs[s];
            #pragma unroll
            for (int r = 0; r < 4; ++r) {
                s1 += c1sh[s * 4 + r] * (kv[r] * qu[r]);
                s2 += c2sh[s * 4 + r] * (kv[r] - qu[r]);
            }
            aa[p * 9 + s]     = tanhf(s1);
            aa[p * 9 + 4 + s] = tanhf(s2);
        }
    }
    __syncthreads();

    // phase B: 32 o's, p-coalesced stores
    int o0 = oh * 32;
    for (int o = o0; o < o0 + 32; ++o) {
        float w0 = fwal[o*8+0], w1 = fwal[o*8+1], w2 = fwal[o*8+2], w3 = fwal[o*8+3];
        float w4 = fwal[o*8+4], w5 = fwal[o*8+5], w6 = fwal[o*8+6], w7 = fwal[o*8+7];
        float fb_ = fbal[o];
        float* dst = g_att + (size_t)(n * cO + o) * 625;
        for (int p = tid; p < 625; p += 256) {
            const float* a = aa + p * 9;
            float acc = fb_ + adjsh[p];
            acc += w0 * a[0]; acc += w1 * a[1]; acc += w2 * a[2]; acc += w3 * a[3];
            acc += w4 * a[4]; acc += w5 * a[5]; acc += w6 * a[6]; acc += w7 * a[7];
            dst[p] = acc;
        }
    }
}

// ---------------------------------------------------------------------------
// K3: vten[n,o,i] = sum_c Wv[o,c] * x[n,c,i] + bv[o]   (FMA-bound, keep)
// ---------------------------------------------------------------------------
constexpr int CH = 128;  // i-chunk

__global__ void __launch_bounds__(128, 4) k_vten(
    const float* __restrict__ x, const float* __restrict__ Wv,
    const float* __restrict__ bv) {
    extern __shared__ float sm[];
    float* xs  = sm;                    // [64][128]
    ull*   wp  = (ull*)(sm + cC * CH);  // [32 o-pairs][64 c]

    int n  = blockIdx.y;
    int i0 = blockIdx.x * CH;
    int tid = threadIdx.x;

    for (int i = tid; i < cC * (CH / 4); i += 128) {
        int c = i >> 5, j = i & 31;
        ((float4*)xs)[i] =
            ((const float4*)(x + (size_t)(n * cC + c) * TV + i0))[j];
    }
    for (int i = tid; i < 32 * cC; i += 128) {
        int pp = i >> 6, c = i & 63;
        ((float2*)wp)[i] = make_float2(Wv[(2 * pp) * cC + c],
                                       Wv[(2 * pp + 1) * cC + c]);
    }
    __syncthreads();

    int osub = tid >> 4;
    int tug  = tid & 15;
    int tu0  = tug * 8;
    const ull* wbase = wp + (osub * 4) * cC;

    ull acc[4][8];
    #pragma unroll
    for (int pp = 0; pp < 4; ++pp)
        #pragma unroll
        for (int j = 0; j < 8; ++j) acc[pp][j] = 0ull;

    #pragma unroll 4
    for (int c = 0; c < cC; ++c) {
        float4 xa = *(const float4*)(xs + c * CH + tu0);
        float4 xb = *(const float4*)(xs + c * CH + tu0 + 4);
        ull xd[8];
        asm("mov.b64 %0, {%1, %1};" : "=l"(xd[0]) : "f"(xa.x));
        asm("mov.b64 %0, {%1, %1};" : "=l"(xd[1]) : "f"(xa.y));
        asm("mov.b64 %0, {%1, %1};" : "=l"(xd[2]) : "f"(xa.z));
        asm("mov.b64 %0, {%1, %1};" : "=l"(xd[3]) : "f"(xa.w));
        asm("mov.b64 %0, {%1, %1};" : "=l"(xd[4]) : "f"(xb.x));
        asm("mov.b64 %0, {%1, %1};" : "=l"(xd[5]) : "f"(xb.y));
        asm("mov.b64 %0, {%1, %1};" : "=l"(xd[6]) : "f"(xb.z));
        asm("mov.b64 %0, {%1, %1};" : "=l"(xd[7]) : "f"(xb.w));
        #pragma unroll
        for (int pp = 0; pp < 4; ++pp) {
            ull w = wbase[pp * cC + c];
            #pragma unroll
            for (int j = 0; j < 8; ++j)
                asm("fma.rn.f32x2 %0, %1, %2, %0;"
                    : "+l"(acc[pp][j]) : "l"(xd[j]), "l"(w));
        }
    }

    #pragma unroll
    for (int pp = 0; pp < 4; ++pp) {
        int olo = osub * 8 + 2 * pp;
        float blo = __ldg(bv + olo), bhi = __ldg(bv + olo + 1);
        float lo[8], hi[8];
        #pragma unroll
        for (int j = 0; j < 8; ++j)
            asm("mov.b64 {%0, %1}, %2;" : "=f"(lo[j]), "=f"(hi[j]) : "l"(acc[pp][j]));
        float* plo = g_vten + (size_t)(n * cO + olo) * TV + i0 + tu0;
        float* phi = plo + TV;
        ((float4*)plo)[0] = make_float4(lo[0]+blo, lo[1]+blo, lo[2]+blo, lo[3]+blo);
        ((float4*)plo)[1] = make_float4(lo[4]+blo, lo[5]+blo, lo[6]+blo, lo[7]+blo);
        ((float4*)phi)[0] = make_float4(hi[0]+bhi, hi[1]+bhi, hi[2]+bhi, hi[3]+bhi);
        ((float4*)phi)[1] = make_float4(hi[4]+bhi, hi[5]+bhi, hi[6]+bhi, hi[7]+bhi);
    }
}

// ---------------------------------------------------------------------------
// K4: out[n,o,t,v] = sum_u att[n,o,v,u] * vten[n,o,t,u]
// grid (32, N): o-pairs. 320 THREADS (launch must match!):
//   warps w=0..9: oi = w>=5, vq = w%5, tg = tid&31.
//   thread tile: 5 v (vq*5+vi) x 4 t (ti*32+tg), f32x2 paired over u.
// Both operands u-contiguous: no packing movs, no transposes. Rows padded to
// 26 floats, zero at u=25; stride 13 ull -> conflict-free LDS.64.
// Staging & writeback by row ownership: no div/mod anywhere.
// ---------------------------------------------------------------------------
constexpr int RS = 26;   // row stride (floats) for both vt and att tiles

__global__ void __launch_bounds__(320, 2) k_out(float* __restrict__ out) {
    __shared__ __align__(16) float vtr[2 * cT * RS];     // 6656 fl
    __shared__ __align__(16) float ash[2 * cV * RS];     // 1300 fl

    int n  = blockIdx.y;
    int op = blockIdx.x;
    int tid = threadIdx.x;
    int obase = n * cO + op * 2;

    // stage vt: thread (oi,t) owns one 25-float row (+pad)
    if (tid < 256) {
        int oi = tid >> 7, t = tid & 127;
        const float* src = g_vten + (size_t)(obase + oi) * TV + t * cV;
        float* dst = vtr + oi * (cT * RS) + t * RS;
        float r[25];
        #pragma unroll
        for (int u = 0; u < 25; ++u) r[u] = src[u];
        #pragma unroll
        for (int up = 0; up < 12; ++up)
            *(float2*)(dst + 2 * up) = make_float2(r[2 * up], r[2 * up + 1]);
        *(float2*)(dst + 24) = make_float2(r[24], 0.f);
    } else {
        int j = tid - 256;                 // 50 att rows on tids 256..305
        if (j < 50) {
            int oi = (j >= 25) ? 1 : 0;
            int v  = j - 25 * oi;
            const float* src = g_att + (size_t)(obase + oi) * 625 + v * cV;
            float* dst = ash + oi * (cV * RS) + v * RS;
            float r[25];
            #pragma unroll
            for (int u = 0; u < 25; ++u) r[u] = src[u];
            #pragma unroll
            for (int up = 0; up < 12; ++up)
                *(float2*)(dst + 2 * up) = make_float2(r[2 * up], r[2 * up + 1]);
            *(float2*)(dst + 24) = make_float2(r[24], 0.f);
        }
    }
    __syncthreads();

    int w  = tid >> 5;
    int tg = tid & 31;
    int oi = (w >= 5) ? 1 : 0;
    int vq = w - 5 * oi;

    const ull* ab  = (const ull*)(ash + oi * (cV * RS) + (vq * 5) * RS); // +vi*13
    const ull* vbb = (const ull*)(vtr + oi * (cT * RS)) + tg * (RS / 2); // +ti*32*13

    ull acc[5][4];
    #pragma unroll
    for (int vi = 0; vi < 5; ++vi)
        #pragma unroll
        for (int ti = 0; ti < 4; ++ti) acc[vi][ti] = 0ull;

    #pragma unroll
    for (int up = 0; up < 13; ++up) {
        ull a_u[5], v_u[4];
        #pragma unroll
        for (int vi = 0; vi < 5; ++vi) a_u[vi] = ab[vi * 13 + up];         // broadcast
        #pragma unroll
        for (int ti = 0; ti < 4; ++ti) v_u[ti] = vbb[ti * (32 * 13) + up]; // cf
        #pragma unroll
        for (int vi = 0; vi < 5; ++vi)
            #pragma unroll
            for (int ti = 0; ti < 4; ++ti)
                asm("fma.rn.f32x2 %0, %1, %2, %0;"
                    : "+l"(acc[vi][ti]) : "l"(a_u[vi]), "l"(v_u[ti]));
    }

    // direct writeback: all offsets compile-time relative to per-thread base
    float* ob = out + (size_t)(obase + oi) * TV + tg * cV + vq * 5;
    #pragma unroll
    for (int ti = 0; ti < 4; ++ti) {
        #pragma unroll
        for (int vi = 0; vi < 5; ++vi) {
            float lo, hi;
            asm("mov.b64 {%0, %1}, %2;" : "=f"(lo), "=f"(hi) : "l"(acc[vi][ti]));
            ob[ti * (32 * cV) + vi] = lo + hi;
        }
    }
}

// ---------------------------------------------------------------------------
extern "C" void kernel_launch(void* const* d_in, const int* in_sizes, int n_in,
                              void* d_out, int out_size) {
    const float* x    = (const float*)d_in[0];
    const float* adj  = (const float*)d_in[1];
    const float* Wk   = (const float*)d_in[2];
    const float* bk   = (const float*)d_in[3];
    const float* Wq   = (const float*)d_in[4];
    const float* bq   = (const float*)d_in[5];
    const float* Wv   = (const float*)d_in[6];
    const float* bv   = (const float*)d_in[7];
    const float* c1w  = (const float*)d_in[8];
    const float* c1b  = (const float*)d_in[9];
    const float* c2w  = (const float*)d_in[10];
    const float* c2b  = (const float*)d_in[11];
    const float* fw   = (const float*)d_in[12];
    const float* fb   = (const float*)d_in[13];
    const float* alpha= (const float*)d_in[14];
    float* out = (float*)d_out;

    int vten_smem = (cC * CH + 32 * cC * 2) * (int)sizeof(float);  // 49152
    cudaFuncSetAttribute((const void*)k_vten,
                         cudaFuncAttributeMaxDynamicSharedMemorySize, vten_smem);

    k_sum_t<<<dim3(8, cN), 256>>>(x);
    k_att_kernel<<<dim3(2, cN), 256>>>(adj, Wk, bk, Wq, bq, c1w, c1b, c2w, c2b, fw, fb, alpha);
    k_vten<<<dim3(TV / CH, cN), 128, vten_smem>>>(x, Wv, bv);
    k_out<<<dim3(cO / 2, cN), 320>>>(out);   // MUST be 320 (10 warps + stagers)
}

// round 12
// speedup vs baseline: 1.3483x; 1.3483x over previous
#include <cuda_runtime.h>

typedef unsigned long long ull;

constexpr int cN = 256, cC = 64, cT = 128, cV = 25, cO = 64;
constexpr int TV  = cT * cV;          // 3200 contiguous (t,v) per (n, channel)

// scratch (no allocations allowed)
__device__ float g_xsum[cN * cC * cV];                    // 1.6 MB
__device__ float g_att[(size_t)cN * cO * cV * cV];        // 41 MB
__device__ float g_vten[(size_t)cN * cO * TV];            // 210 MB

// ---------------------------------------------------------------------------
// K1: xsum[n,c,v] = sum_t x[n,c,t,v]   (HBM-roof bound, ~40us, keep)
// ---------------------------------------------------------------------------
__global__ void k_sum_t(const float* __restrict__ x) {
    int n = blockIdx.y;
    int c = blockIdx.x * 8 + (threadIdx.x >> 5);
    int lane = threadIdx.x & 31;
    if (lane < cV) {
        const float* p = x + ((size_t)(n * cC + c) * cT) * cV + lane;
        float s = 0.f;
        #pragma unroll 8
        for (int t = 0; t < cT; ++t) s += p[t * cV];
        g_xsum[(n * cC + c) * cV + lane] = s;
    }
}

// ---------------------------------------------------------------------------
// K2: attention matrix (fast since R11, keep)
// ---------------------------------------------------------------------------
__global__ void __launch_bounds__(256) k_att_kernel(
    const float* __restrict__ adj,
    const float* __restrict__ Wk, const float* __restrict__ bk,
    const float* __restrict__ Wq, const float* __restrict__ bq,
    const float* __restrict__ c1w, const float* __restrict__ c1b,
    const float* __restrict__ c2w, const float* __restrict__ c2b,
    const float* __restrict__ fw,  const float* __restrict__ fb,
    const float* __restrict__ alpha) {
    __shared__ float xs2[cC * cV];
    __shared__ float ksh[4 * cV], qsh[4 * cV];
    __shared__ float fwal[cO * 8];              // alpha * fw
    __shared__ float adjsh[cV * cV];
    __shared__ float aa[625 * 9];               // tanh features, stride 9
    __shared__ float c1sh[16], c2sh[16], c1bs[4], c2bs[4], fbal[cO], bks[4], bqs[4];

    int n = blockIdx.y, oh = blockIdx.x, tid = threadIdx.x;
    float al = alpha[0];
    for (int i = tid; i < cC * cV; i += 256) xs2[i] = g_xsum[n * cC * cV + i];
    for (int i = tid; i < cO * 8; i += 256)  fwal[i] = al * fw[i];
    for (int i = tid; i < cV * cV; i += 256) adjsh[i] = adj[i];
    if (tid < 16) { c1sh[tid] = c1w[tid]; c2sh[tid] = c2w[tid]; }
    if (tid < 4)  { c1bs[tid] = c1b[tid]; c2bs[tid] = c2b[tid]; bks[tid] = bk[tid]; bqs[tid] = bq[tid]; }
    if (tid < cO) fbal[tid] = al * fb[tid];
    __syncthreads();

    if (tid < 100) {
        int r = tid / cV, v = tid % cV;
        float a = 0.f;
        for (int c = 0; c < cC; ++c) a += Wk[r * cC + c] * xs2[c * cV + v];
        ksh[tid] = a * (1.f / cT) + bks[r];
    } else if (tid < 200) {
        int j = tid - 100;
        int r = j / cV, v = j % cV;
        float a = 0.f;
        for (int c = 0; c < cC; ++c) a += Wq[r * cC + c] * xs2[c * cV + v];
        qsh[j] = a * (1.f / cT) + bqs[r];
    }
    __syncthreads();

    for (int p = tid; p < 625; p += 256) {
        int v = p / cV, u = p - v * cV;
        float kv[4], qu[4];
        #pragma unroll
        for (int r = 0; r < 4; ++r) { kv[r] = ksh[r * cV + v]; qu[r] = qsh[r * cV + u]; }
        #pragma unroll
        for (int s = 0; s < 4; ++s) {
            float s1 = c1bs[s], s2 = c2bs[s];
            #pragma unroll
            for (int r = 0; r < 4; ++r) {
                s1 += c1sh[s * 4 + r] * (kv[r] * qu[r]);
                s2 += c2sh[s * 4 + r] * (kv[r] - qu[r]);
            }
            aa[p * 9 + s]     = tanhf(s1);
            aa[p * 9 + 4 + s] = tanhf(s2);
        }
    }
    __syncthreads();

    int o0 = oh * 32;
    for (int o = o0; o < o0 + 32; ++o) {
        float w0 = fwal[o*8+0], w1 = fwal[o*8+1], w2 = fwal[o*8+2], w3 = fwal[o*8+3];
        float w4 = fwal[o*8+4], w5 = fwal[o*8+5], w6 = fwal[o*8+6], w7 = fwal[o*8+7];
        float fb_ = fbal[o];
        float* dst = g_att + (size_t)(n * cO + o) * 625;
        for (int p = tid; p < 625; p += 256) {
            const float* a = aa + p * 9;
            float acc = fb_ + adjsh[p];
            acc += w0 * a[0]; acc += w1 * a[1]; acc += w2 * a[2]; acc += w3 * a[3];
            acc += w4 * a[4]; acc += w5 * a[5]; acc += w6 * a[6]; acc += w7 * a[7];
            dst[p] = acc;
        }
    }
}

// ---------------------------------------------------------------------------
// K3: vten[n,o,i] = sum_c Wv[o,c] * x[n,c,i] + bv[o]
// CONFLICT FIX: tu0 = tug*4, second float4 at +64 -> each LDS.128 covers a
// 256B-contiguous half-warp span (bank-conflict-free) instead of stride-32B
// (4-way conflict). Gmem stores remain coalesced (16 consecutive float4).
// ---------------------------------------------------------------------------
constexpr int CH = 128;  // i-chunk

__global__ void __launch_bounds__(128, 4) k_vten(
    const float* __restrict__ x, const float* __restrict__ Wv,
    const float* __restrict__ bv) {
    extern __shared__ float sm[];
    float* xs  = sm;                    // [64][128]
    ull*   wp  = (ull*)(sm + cC * CH);  // [32 o-pairs][64 c]

    int n  = blockIdx.y;
    int i0 = blockIdx.x * CH;
    int tid = threadIdx.x;

    for (int i = tid; i < cC * (CH / 4); i += 128) {
        int c = i >> 5, j = i & 31;
        ((float4*)xs)[i] =
            ((const float4*)(x + (size_t)(n * cC + c) * TV + i0))[j];
    }
    for (int i = tid; i < 32 * cC; i += 128) {
        int pp = i >> 6, c = i & 63;
        ((float2*)wp)[i] = make_float2(Wv[(2 * pp) * cC + c],
                                       Wv[(2 * pp + 1) * cC + c]);
    }
    __syncthreads();

    int osub = tid >> 4;
    int tug  = tid & 15;
    int tu0  = tug * 4;                 // contiguous 16B per lane
    const ull* wbase = wp + (osub * 4) * cC;

    ull acc[4][8];
    #pragma unroll
    for (int pp = 0; pp < 4; ++pp)
        #pragma unroll
        for (int j = 0; j < 8; ++j) acc[pp][j] = 0ull;

    #pragma unroll 4
    for (int c = 0; c < cC; ++c) {
        float4 xa = *(const float4*)(xs + c * CH + tu0);        // conflict-free
        float4 xb = *(const float4*)(xs + c * CH + 64 + tu0);   // conflict-free
        ull xd[8];
        asm("mov.b64 %0, {%1, %1};" : "=l"(xd[0]) : "f"(xa.x));
        asm("mov.b64 %0, {%1, %1};" : "=l"(xd[1]) : "f"(xa.y));
        asm("mov.b64 %0, {%1, %1};" : "=l"(xd[2]) : "f"(xa.z));
        asm("mov.b64 %0, {%1, %1};" : "=l"(xd[3]) : "f"(xa.w));
        asm("mov.b64 %0, {%1, %1};" : "=l"(xd[4]) : "f"(xb.x));
        asm("mov.b64 %0, {%1, %1};" : "=l"(xd[5]) : "f"(xb.y));
        asm("mov.b64 %0, {%1, %1};" : "=l"(xd[6]) : "f"(xb.z));
        asm("mov.b64 %0, {%1, %1};" : "=l"(xd[7]) : "f"(xb.w));
        #pragma unroll
        for (int pp = 0; pp < 4; ++pp) {
            ull w = wbase[pp * cC + c];
            #pragma unroll
            for (int j = 0; j < 8; ++j)
                asm("fma.rn.f32x2 %0, %1, %2, %0;"
                    : "+l"(acc[pp][j]) : "l"(xd[j]), "l"(w));
        }
    }

    #pragma unroll
    for (int pp = 0; pp < 4; ++pp) {
        int olo = osub * 8 + 2 * pp;
        float blo = __ldg(bv + olo), bhi = __ldg(bv + olo + 1);
        float lo[8], hi[8];
        #pragma unroll
        for (int j = 0; j < 8; ++j)
            asm("mov.b64 {%0, %1}, %2;" : "=f"(lo[j]), "=f"(hi[j]) : "l"(acc[pp][j]));
        float* plo = g_vten + (size_t)(n * cO + olo) * TV + i0;
        float* phi = plo + TV;
        *(float4*)(plo + tu0)      = make_float4(lo[0]+blo, lo[1]+blo, lo[2]+blo, lo[3]+blo);
        *(float4*)(plo + 64 + tu0) = make_float4(lo[4]+blo, lo[5]+blo, lo[6]+blo, lo[7]+blo);
        *(float4*)(phi + tu0)      = make_float4(hi[0]+bhi, hi[1]+bhi, hi[2]+bhi, hi[3]+bhi);
        *(float4*)(phi + 64 + tu0) = make_float4(hi[4]+bhi, hi[5]+bhi, hi[6]+bhi, hi[7]+bhi);
    }
}

// ---------------------------------------------------------------------------
// K4: out[n,o,t,v] = sum_u att[n,o,v,u] * vten[n,o,t,u]
// grid (32, N): o-pairs, 320 threads, 3 blocks/SM.
// COALESCING FIX: all gmem access is linear stride-1 (vten rows for the
// o-pair are contiguous: 6400 floats; att: 1250 floats). Pad/unpad transforms
// happen via smem scatter/gather (conflict-free). Mainloop unchanged from
// the verified R11 version (u-paired f32x2, stride-13 ull rows).
// ---------------------------------------------------------------------------
constexpr int RS = 26;   // padded row stride (floats)

__global__ void __launch_bounds__(320, 3) k_out(float* __restrict__ out) {
    __shared__ __align__(16) float vtr[2 * cT * RS];     // 6656 fl; reused as outsh (6400)
    __shared__ __align__(16) float ash[2 * cV * RS];     // 1300 fl

    int n  = blockIdx.y;
    int op = blockIdx.x;
    int tid = threadIdx.x;
    int obase = n * cO + op * 2;

    // ---- stage vt: linear coalesced gmem read, smem scatter into padded rows
    const float* vsrc = g_vten + (size_t)obase * TV;     // 6400 contiguous
    #pragma unroll
    for (int k = 0; k < 20; ++k) {                       // 20*320 = 6400
        int i  = k * 320 + tid;
        float d = vsrc[i];
        int oi2 = (i >= TV);
        int r  = i - oi2 * TV;
        int t  = r / cV, u = r - t * cV;                 // magic-mul div
        vtr[oi2 * (cT * RS) + t * RS + u] = d;
    }
    // ---- stage att: 1250 contiguous floats
    const float* asrc = g_att + (size_t)obase * 625;
    for (int i = tid; i < 1250; i += 320) {
        float d = asrc[i];
        int oi2 = (i >= 625);
        int r  = i - oi2 * 625;
        int v  = r / cV, u = r - v * cV;
        ash[oi2 * (cV * RS) + v * RS + u] = d;
    }
    // ---- zero pad columns (u = 25)
    if (tid < 256) {
        int oi2 = tid >> 7, t = tid & 127;
        vtr[oi2 * (cT * RS) + t * RS + cV] = 0.f;
    } else if (tid < 306) {
        int j = tid - 256;
        int oi2 = (j >= 25) ? 1 : 0;
        int v = j - 25 * oi2;
        ash[oi2 * (cV * RS) + v * RS + cV] = 0.f;
    }
    __syncthreads();

    int w  = tid >> 5;
    int tg = tid & 31;
    int oi = (w >= 5) ? 1 : 0;
    int vq = w - 5 * oi;

    const ull* ab  = (const ull*)(ash + oi * (cV * RS) + (vq * 5) * RS); // +vi*13
    const ull* vbb = (const ull*)(vtr + oi * (cT * RS)) + tg * (RS / 2); // +ti*32*13

    ull acc[5][4];
    #pragma unroll
    for (int vi = 0; vi < 5; ++vi)
        #pragma unroll
        for (int ti = 0; ti < 4; ++ti) acc[vi][ti] = 0ull;

    #pragma unroll
    for (int up = 0; up < 13; ++up) {
        ull a_u[5], v_u[4];
        #pragma unroll
        for (int vi = 0; vi < 5; ++vi) a_u[vi] = ab[vi * 13 + up];         // broadcast
        #pragma unroll
        for (int ti = 0; ti < 4; ++ti) v_u[ti] = vbb[ti * (32 * 13) + up]; // cf
        #pragma unroll
        for (int vi = 0; vi < 5; ++vi)
            #pragma unroll
            for (int ti = 0; ti < 4; ++ti)
                asm("fma.rn.f32x2 %0, %1, %2, %0;"
                    : "+l"(acc[vi][ti]) : "l"(a_u[vi]), "l"(v_u[ti]));
    }
    __syncthreads();   // all reads of vtr done -> reuse as output buffer

    // ---- results into smem (unpadded t*25+v; lane stride 25 -> conflict-free)
    float* outsh = vtr;
    #pragma unroll
    for (int ti = 0; ti < 4; ++ti) {
        int t = ti * 32 + tg;
        #pragma unroll
        for (int vi = 0; vi < 5; ++vi) {
            float lo, hi;
            asm("mov.b64 {%0, %1}, %2;" : "=f"(lo), "=f"(hi) : "l"(acc[vi][ti]));
            outsh[oi * TV + t * cV + vq * 5 + vi] = lo + hi;
        }
    }
    __syncthreads();

    // ---- linear coalesced writeback
    float* odst = out + (size_t)obase * TV;
    #pragma unroll
    for (int k = 0; k < 20; ++k) {
        int i = k * 320 + tid;
        odst[i] = outsh[i];
    }
}

// ---------------------------------------------------------------------------
extern "C" void kernel_launch(void* const* d_in, const int* in_sizes, int n_in,
                              void* d_out, int out_size) {
    const float* x    = (const float*)d_in[0];
    const float* adj  = (const float*)d_in[1];
    const float* Wk   = (const float*)d_in[2];
    const float* bk   = (const float*)d_in[3];
    const float* Wq   = (const float*)d_in[4];
    const float* bq   = (const float*)d_in[5];
    const float* Wv   = (const float*)d_in[6];
    const float* bv   = (const float*)d_in[7];
    const float* c1w  = (const float*)d_in[8];
    const float* c1b  = (const float*)d_in[9];
    const float* c2w  = (const float*)d_in[10];
    const float* c2b  = (const float*)d_in[11];
    const float* fw   = (const float*)d_in[12];
    const float* fb   = (const float*)d_in[13];
    const float* alpha= (const float*)d_in[14];
    float* out = (float*)d_out;

    int vten_smem = (cC * CH + 32 * cC * 2) * (int)sizeof(float);  // 49152
    cudaFuncSetAttribute((const void*)k_vten,
                         cudaFuncAttributeMaxDynamicSharedMemorySize, vten_smem);

    k_sum_t<<<dim3(8, cN), 256>>>(x);
    k_att_kernel<<<dim3(2, cN), 256>>>(adj, Wk, bk, Wq, bq, c1w, c1b, c2w, c2b, fw, fb, alpha);
    k_vten<<<dim3(TV / CH, cN), 128, vten_smem>>>(x, Wv, bv);
    k_out<<<dim3(cO / 2, cN), 320>>>(out);
}